// round 3
// baseline (speedup 1.0000x reference)
#include <cuda_runtime.h>
#include <cuda_bf16.h>
#include <cstdint>

// ---------------- problem dims ----------------
#define GM 16384
#define GN 4096
#define GK 4096
#define BM 128
#define BN 256
#define BK 64
#define NKI (GK / BK)          // 64 k-chunks
#define STAGES 4
#define ROWB 80                // padded smem row stride (64B data + 16B pad): bank-safe
#define A_STAGE (BM * ROWB)    // 10240
#define B_STAGE (BN * ROWB)    // 20480
#define STAGE_BYTES (A_STAGE + B_STAGE)   // 30720
#define SMEM_REQ (STAGES * STAGE_BYTES)   // 122880

// ---------------- device scratch (static, allocation-free) ----------------
__device__ unsigned g_amax_bits[2];                 // [0]=x, [1]=w (fp32 bits, >=0)
__device__ int8_t g_qx[(size_t)GM * GK];            // 64 MB
__device__ int8_t g_qw[(size_t)GN * GK];            // 16 MB

// ---------------- PTX helpers (base sm_103 target only) ----------------
__device__ __forceinline__ uint32_t smem_u32(const void* p) {
    uint32_t a;
    asm("{ .reg .u64 t; cvta.to.shared.u64 t, %1; cvt.u32.u64 %0, t; }" : "=r"(a) : "l"(p));
    return a;
}

#define CP_ASYNC_16(dst, src) \
    asm volatile("cp.async.cg.shared.global [%0], [%1], 16;" :: "r"(dst), "l"(src) : "memory")
#define CP_COMMIT() asm volatile("cp.async.commit_group;" ::: "memory")
#define CP_WAIT(n)  asm volatile("cp.async.wait_group %0;" :: "n"(n) : "memory")

__device__ __forceinline__ void ldsm4(uint32_t addr, uint32_t& r0, uint32_t& r1,
                                      uint32_t& r2, uint32_t& r3) {
    asm volatile("ldmatrix.sync.aligned.m8n8.x4.shared.b16 {%0,%1,%2,%3}, [%4];"
                 : "=r"(r0), "=r"(r1), "=r"(r2), "=r"(r3) : "r"(addr));
}

__device__ __forceinline__ void imma(int* d, const uint32_t* a, uint32_t b0, uint32_t b1) {
    asm volatile(
        "mma.sync.aligned.m16n8k32.row.col.s32.s8.s8.s32 "
        "{%0,%1,%2,%3}, {%4,%5,%6,%7}, {%8,%9}, {%0,%1,%2,%3};"
        : "+r"(d[0]), "+r"(d[1]), "+r"(d[2]), "+r"(d[3])
        : "r"(a[0]), "r"(a[1]), "r"(a[2]), "r"(a[3]), "r"(b0), "r"(b1));
}

// ---------------- prep kernels ----------------
__global__ void init_kernel() {
    g_amax_bits[0] = 0u;
    g_amax_bits[1] = 0u;
}

__global__ void absmax_kernel(const float4* __restrict__ in, long n4, unsigned* __restrict__ out_bits) {
    float m = 0.0f;
    for (long i = blockIdx.x * (long)blockDim.x + threadIdx.x; i < n4; i += (long)gridDim.x * blockDim.x) {
        float4 v = in[i];
        m = fmaxf(m, fmaxf(fmaxf(fabsf(v.x), fabsf(v.y)), fmaxf(fabsf(v.z), fabsf(v.w))));
    }
#pragma unroll
    for (int o = 16; o; o >>= 1) m = fmaxf(m, __shfl_xor_sync(0xffffffffu, m, o));
    __shared__ float sm[8];
    int wid = threadIdx.x >> 5;
    if ((threadIdx.x & 31) == 0) sm[wid] = m;
    __syncthreads();
    if (threadIdx.x == 0) {
        float b = sm[0];
        for (int w = 1; w < (int)(blockDim.x >> 5); w++) b = fmaxf(b, sm[w]);
        atomicMax(out_bits, __float_as_uint(b));   // values >= 0: uint order == float order
    }
}

// quantize to int8 codes (round-to-nearest-even matches jnp.round)
__global__ void quant_kernel(const float4* __restrict__ in, char4* __restrict__ out,
                             const unsigned* __restrict__ amax_bits) {
    long i = blockIdx.x * (long)blockDim.x + threadIdx.x;
    float amax = __uint_as_float(*amax_bits);
    float scale = fmaxf(amax / 127.0f, 1e-8f);
    float4 v = in[i];
    int q0 = (int)fminf(127.0f, fmaxf(-127.0f, rintf(v.x / scale)));
    int q1 = (int)fminf(127.0f, fmaxf(-127.0f, rintf(v.y / scale)));
    int q2 = (int)fminf(127.0f, fmaxf(-127.0f, rintf(v.z / scale)));
    int q3 = (int)fminf(127.0f, fmaxf(-127.0f, rintf(v.w / scale)));
    out[i] = make_char4((signed char)q0, (signed char)q1, (signed char)q2, (signed char)q3);
}

// ---------------- GEMM: 128x256x64, 512 thr, 4-stage cp.async, IMMA ----------------
__global__ void __launch_bounds__(512, 1) gemm_kernel(
    const int8_t* __restrict__ qa,      // [GM, GK]
    const int8_t* __restrict__ qb,      // [GN, GK]
    const float* __restrict__ bias,
    float* __restrict__ out,
    const unsigned* __restrict__ amax_bits)
{
    extern __shared__ char smem_raw[];
    const uint32_t tiles = smem_u32(smem_raw);

    const int tid  = threadIdx.x;
    const int wid  = tid >> 5;
    const int lane = tid & 31;
    const int wm   = (wid & 3) * 32;    // warp M offset in tile
    const int wn   = (wid >> 2) * 64;   // warp N offset in tile

    const int m0 = blockIdx.y * BM;
    const int n0 = blockIdx.x * BN;

    // ---- cp.async thread mapping ----
    // A: 512 chunks of 16B -> 1/thread: row = tid>>2, c = tid&3
    // B: 1024 chunks      -> 2/thread: rows tid>>2 and (tid>>2)+128
    const int cp_row = tid >> 2;
    const int cp_c   = tid & 3;
    const int8_t* gA = qa + (size_t)(m0 + cp_row) * GK + cp_c * 16;
    const int8_t* gB0 = qb + (size_t)(n0 + cp_row) * GK + cp_c * 16;
    const int8_t* gB1 = qb + (size_t)(n0 + cp_row + 128) * GK + cp_c * 16;
    const uint32_t sA_off = (uint32_t)cp_row * ROWB + cp_c * 16;
    const uint32_t sB0_off = A_STAGE + (uint32_t)cp_row * ROWB + cp_c * 16;
    const uint32_t sB1_off = A_STAGE + (uint32_t)(cp_row + 128) * ROWB + cp_c * 16;

    // ---- ldmatrix per-thread address offsets ----
    // A x4 (fragment order a0,a1,a2,a3 = row-half-first):
    //   t0-7   -> rows 0-7,  k bytes 0-15   (matrix0 = a0)
    //   t8-15  -> rows 8-15, k bytes 0-15   (matrix1 = a1)
    //   t16-23 -> rows 0-7,  k bytes 16-31  (matrix2 = a2)
    //   t24-31 -> rows 8-15, k bytes 16-31  (matrix3 = a3)
    const int a_row = (lane & 7) + ((lane >> 3) & 1) * 8;
    const int a_col = (lane >> 4) * 16;
    const uint32_t a_base = (uint32_t)(wm + a_row) * ROWB + a_col;
    // B x4: t0-7 -> n 0-7 k 0-15 (b0, mma0); t8-15 -> n 0-7 k 16-31 (b1, mma0);
    //       t16-23 -> n 8-15 k 0-15 (b0, mma1); t24-31 -> n 8-15 k 16-31 (b1, mma1)
    const int b_row = (lane & 7) + ((lane >> 4) & 1) * 8;
    const int b_col = ((lane >> 3) & 1) * 16;
    const uint32_t b_base = A_STAGE + (uint32_t)(wn + b_row) * ROWB + b_col;

    int acc[2][8][4];
#pragma unroll
    for (int i = 0; i < 2; i++)
#pragma unroll
        for (int j = 0; j < 8; j++)
#pragma unroll
            for (int r = 0; r < 4; r++) acc[i][j][r] = 0;

    // ---- prologue: fill STAGES-1 stages ----
#pragma unroll
    for (int s = 0; s < STAGES - 1; s++) {
        const uint32_t sb = tiles + s * STAGE_BYTES;
        const int k0 = s * BK;
        CP_ASYNC_16(sb + sA_off, gA + k0);
        CP_ASYNC_16(sb + sB0_off, gB0 + k0);
        CP_ASYNC_16(sb + sB1_off, gB1 + k0);
        CP_COMMIT();
    }

    // ---- mainloop ----
    for (int ki = 0; ki < NKI; ki++) {
        CP_WAIT(STAGES - 2);
        __syncthreads();

        // prefetch stage ki+STAGES-1
        {
            const int kj = ki + STAGES - 1;
            if (kj < NKI) {
                const uint32_t sb = tiles + (kj & (STAGES - 1)) * STAGE_BYTES;
                const int k0 = kj * BK;
                CP_ASYNC_16(sb + sA_off, gA + k0);
                CP_ASYNC_16(sb + sB0_off, gB0 + k0);
                CP_ASYNC_16(sb + sB1_off, gB1 + k0);
            }
            CP_COMMIT();
        }

        const uint32_t sb = tiles + (ki & (STAGES - 1)) * STAGE_BYTES;
#pragma unroll
        for (int ks = 0; ks < 2; ks++) {
            uint32_t a[2][4];
#pragma unroll
            for (int i = 0; i < 2; i++) {
                uint32_t r0, r1, r2, r3;
                ldsm4(sb + a_base + i * (16 * ROWB) + ks * 32, r0, r1, r2, r3);
                a[i][0] = r0; a[i][1] = r1; a[i][2] = r2; a[i][3] = r3;   // straight {a0,a1,a2,a3}
            }
#pragma unroll
            for (int jj = 0; jj < 4; jj++) {
                uint32_t t0, t1, t2, t3;
                ldsm4(sb + b_base + jj * (16 * ROWB) + ks * 32, t0, t1, t2, t3);
                imma(acc[0][jj * 2 + 0], a[0], t0, t1);
                imma(acc[0][jj * 2 + 1], a[0], t2, t3);
                imma(acc[1][jj * 2 + 0], a[1], t0, t1);
                imma(acc[1][jj * 2 + 1], a[1], t2, t3);
            }
        }
    }

    // ---- epilogue ----
    const float ax = __uint_as_float(amax_bits[0]);
    const float aw = __uint_as_float(amax_bits[1]);
    const float sc = fmaxf(ax / 127.0f, 1e-8f) * fmaxf(aw / 127.0f, 1e-8f);

    const int g = lane >> 2;
    const int q = lane & 3;
#pragma unroll
    for (int i = 0; i < 2; i++) {
        const int row0 = m0 + wm + i * 16 + g;
#pragma unroll
        for (int j = 0; j < 8; j++) {
            const int col = n0 + wn + j * 8 + q * 2;
            const float2 bv = __ldg(reinterpret_cast<const float2*>(bias + col));
            float2 o0, o1;
            o0.x = fmaf((float)acc[i][j][0], sc, bv.x);
            o0.y = fmaf((float)acc[i][j][1], sc, bv.y);
            o1.x = fmaf((float)acc[i][j][2], sc, bv.x);
            o1.y = fmaf((float)acc[i][j][3], sc, bv.y);
            *reinterpret_cast<float2*>(out + (size_t)row0 * GN + col) = o0;
            *reinterpret_cast<float2*>(out + (size_t)(row0 + 8) * GN + col) = o1;
        }
    }
}

// ---------------- host launch ----------------
extern "C" void kernel_launch(void* const* d_in, const int* in_sizes, int n_in,
                              void* d_out, int out_size) {
    const float* x    = (const float*)d_in[0];
    const float* w    = (const float*)d_in[1];
    const float* bias = (const float*)d_in[2];
    float* out        = (float*)d_out;

    void *qx_ptr = nullptr, *qw_ptr = nullptr, *amax_ptr = nullptr;
    cudaGetSymbolAddress(&qx_ptr, g_qx);
    cudaGetSymbolAddress(&qw_ptr, g_qw);
    cudaGetSymbolAddress(&amax_ptr, g_amax_bits);
    unsigned* amax = (unsigned*)amax_ptr;

    init_kernel<<<1, 1>>>();
    absmax_kernel<<<2048, 256>>>((const float4*)x, (long)GM * GK / 4, amax + 0);
    absmax_kernel<<<512, 256>>>((const float4*)w, (long)GN * GK / 4, amax + 1);
    quant_kernel<<<65536, 256>>>((const float4*)x, (char4*)qx_ptr, amax + 0);
    quant_kernel<<<16384, 256>>>((const float4*)w, (char4*)qw_ptr, amax + 1);

    cudaFuncSetAttribute(gemm_kernel, cudaFuncAttributeMaxDynamicSharedMemorySize, SMEM_REQ);
    gemm_kernel<<<dim3(GN / BN, GM / BM), 512, SMEM_REQ>>>(
        (const int8_t*)qx_ptr, (const int8_t*)qw_ptr, bias, out, amax);
}

// round 9
// speedup vs baseline: 1.7343x; 1.7343x over previous
#include <cuda_runtime.h>
#include <cuda_bf16.h>
#include <cstdint>

// ---------------- problem dims ----------------
#define GM 16384
#define GN 4096
#define GK 4096
#define BM 128
#define BN 128
#define BK 64
#define NKI (GK / BK)          // 64 k-chunks
#define STAGES 4
#define ROWB 80                // padded smem row stride (64B data + 16B pad): bank-safe
#define A_STAGE (BM * ROWB)    // 10240
#define B_STAGE (BN * ROWB)    // 10240
#define STAGE_BYTES (A_STAGE + B_STAGE)   // 20480
#define SMEM_REQ (STAGES * STAGE_BYTES)   // 81920  -> 2 CTAs/SM

#define N4X ((long)GM * GK / 4)     // 16777216 float4
#define N4W ((long)GN * GK / 4)     // 4194304 float4
#define QBLK_X 65536
#define QBLK_W 16384

// ---------------- device scratch (static, allocation-free) ----------------
__device__ unsigned g_amax_bits[2];                 // [0]=x, [1]=w (fp32 bits, >=0)
__device__ int8_t g_qx[(size_t)GM * GK];            // 64 MB
__device__ int8_t g_qw[(size_t)GN * GK];            // 16 MB

// ---------------- PTX helpers (base sm_103 target only) ----------------
__device__ __forceinline__ uint32_t smem_u32(const void* p) {
    uint32_t a;
    asm("{ .reg .u64 t; cvta.to.shared.u64 t, %1; cvt.u32.u64 %0, t; }" : "=r"(a) : "l"(p));
    return a;
}

#define CP_ASYNC_16(dst, src) \
    asm volatile("cp.async.cg.shared.global [%0], [%1], 16;" :: "r"(dst), "l"(src) : "memory")
#define CP_COMMIT() asm volatile("cp.async.commit_group;" ::: "memory")
#define CP_WAIT(n)  asm volatile("cp.async.wait_group %0;" :: "n"(n) : "memory")

__device__ __forceinline__ void ldsm4(uint32_t addr, uint32_t& r0, uint32_t& r1,
                                      uint32_t& r2, uint32_t& r3) {
    asm volatile("ldmatrix.sync.aligned.m8n8.x4.shared.b16 {%0,%1,%2,%3}, [%4];"
                 : "=r"(r0), "=r"(r1), "=r"(r2), "=r"(r3) : "r"(addr));
}

__device__ __forceinline__ void imma(int* d, const uint32_t* a, uint32_t b0, uint32_t b1) {
    asm volatile(
        "mma.sync.aligned.m16n8k32.row.col.s32.s8.s8.s32 "
        "{%0,%1,%2,%3}, {%4,%5,%6,%7}, {%8,%9}, {%0,%1,%2,%3};"
        : "+r"(d[0]), "+r"(d[1]), "+r"(d[2]), "+r"(d[3])
        : "r"(a[0]), "r"(a[1]), "r"(a[2]), "r"(a[3]), "r"(b0), "r"(b1));
}

// ---------------- prep kernels (fused to keep launch count at 4) ----------------
__global__ void init_kernel() {
    g_amax_bits[0] = 0u;
    g_amax_bits[1] = 0u;
}

// blocks [0, 2048) -> x ; blocks [2048, 2560) -> w
__global__ void absmax_both_kernel(const float4* __restrict__ x, const float4* __restrict__ w) {
    const bool is_x = blockIdx.x < 2048;
    const float4* in = is_x ? x : w;
    const long n4 = is_x ? N4X : N4W;
    const int nb = is_x ? 2048 : 512;
    const int bid = is_x ? blockIdx.x : (blockIdx.x - 2048);

    float m = 0.0f;
    for (long i = bid * (long)blockDim.x + threadIdx.x; i < n4; i += (long)nb * blockDim.x) {
        float4 v = in[i];
        m = fmaxf(m, fmaxf(fmaxf(fabsf(v.x), fabsf(v.y)), fmaxf(fabsf(v.z), fabsf(v.w))));
    }
#pragma unroll
    for (int o = 16; o; o >>= 1) m = fmaxf(m, __shfl_xor_sync(0xffffffffu, m, o));
    __shared__ float sm[8];
    int wid = threadIdx.x >> 5;
    if ((threadIdx.x & 31) == 0) sm[wid] = m;
    __syncthreads();
    if (threadIdx.x == 0) {
        float b = sm[0];
        for (int w2 = 1; w2 < (int)(blockDim.x >> 5); w2++) b = fmaxf(b, sm[w2]);
        atomicMax(&g_amax_bits[is_x ? 0 : 1], __float_as_uint(b));  // vals >= 0: uint order == float order
    }
}

// blocks [0, 65536) -> x ; blocks [65536, 81920) -> w
__global__ void quant_both_kernel(const float4* __restrict__ x, const float4* __restrict__ w,
                                  char4* __restrict__ qx, char4* __restrict__ qw) {
    const bool is_x = blockIdx.x < QBLK_X;
    const float4* in = is_x ? x : w;
    char4* out = is_x ? qx : qw;
    const long bid = is_x ? blockIdx.x : (blockIdx.x - QBLK_X);
    const long i = bid * blockDim.x + threadIdx.x;
    const float amax = __uint_as_float(g_amax_bits[is_x ? 0 : 1]);
    const float inv = 1.0f / fmaxf(amax / 127.0f, 1e-8f);
    float4 v = in[i];
    int q0 = (int)fminf(127.0f, fmaxf(-127.0f, rintf(v.x * inv)));
    int q1 = (int)fminf(127.0f, fmaxf(-127.0f, rintf(v.y * inv)));
    int q2 = (int)fminf(127.0f, fmaxf(-127.0f, rintf(v.z * inv)));
    int q3 = (int)fminf(127.0f, fmaxf(-127.0f, rintf(v.w * inv)));
    out[i] = make_char4((signed char)q0, (signed char)q1, (signed char)q2, (signed char)q3);
}

// ---------------- GEMM: 128x128x64, 256 thr, 2 CTAs/SM, 4-stage cp.async, IMMA ----------------
__global__ void __launch_bounds__(256, 2) gemm_kernel(
    const int8_t* __restrict__ qa,      // [GM, GK]
    const int8_t* __restrict__ qb,      // [GN, GK]
    const float* __restrict__ bias,
    float* __restrict__ out,
    const unsigned* __restrict__ amax_bits)
{
    extern __shared__ char smem_raw[];
    const uint32_t tiles = smem_u32(smem_raw);

    const int tid  = threadIdx.x;
    const int wid  = tid >> 5;
    const int lane = tid & 31;
    const int wm   = (wid & 3) * 32;    // warp M offset in tile (4 warps down)
    const int wn   = (wid >> 2) * 64;   // warp N offset in tile (2 warps across)

    const int m0 = blockIdx.y * BM;
    const int n0 = blockIdx.x * BN;

    // ---- cp.async thread mapping: 256 threads, rows tid>>2 and +64, col chunk tid&3 ----
    const int cp_row = tid >> 2;
    const int cp_c   = tid & 3;
    const int8_t* gA0 = qa + (size_t)(m0 + cp_row) * GK + cp_c * 16;
    const int8_t* gA1 = qa + (size_t)(m0 + cp_row + 64) * GK + cp_c * 16;
    const int8_t* gB0 = qb + (size_t)(n0 + cp_row) * GK + cp_c * 16;
    const int8_t* gB1 = qb + (size_t)(n0 + cp_row + 64) * GK + cp_c * 16;
    const uint32_t sA0 = (uint32_t)cp_row * ROWB + cp_c * 16;
    const uint32_t sA1 = (uint32_t)(cp_row + 64) * ROWB + cp_c * 16;
    const uint32_t sB0 = A_STAGE + (uint32_t)cp_row * ROWB + cp_c * 16;
    const uint32_t sB1 = A_STAGE + (uint32_t)(cp_row + 64) * ROWB + cp_c * 16;

    // ---- ldmatrix per-thread addresses ----
    // A x4 (a0,a1,a2,a3 row-half-first): t0-7 r0-7/k0-15, t8-15 r8-15/k0-15,
    //                                    t16-23 r0-7/k16-31, t24-31 r8-15/k16-31
    const int a_row = (lane & 7) + ((lane >> 3) & 1) * 8;
    const int a_col = (lane >> 4) * 16;
    const uint32_t a_base = (uint32_t)(wm + a_row) * ROWB + a_col;
    // B x4: t0-7 n0-7/k0-15 (b0 of mma0), t8-15 n0-7/k16-31 (b1 of mma0),
    //       t16-23 n8-15/k0-15, t24-31 n8-15/k16-31
    const int b_row = (lane & 7) + ((lane >> 4) & 1) * 8;
    const int b_col = ((lane >> 3) & 1) * 16;
    const uint32_t b_base = A_STAGE + (uint32_t)(wn + b_row) * ROWB + b_col;

    int acc[2][8][4];
#pragma unroll
    for (int i = 0; i < 2; i++)
#pragma unroll
        for (int j = 0; j < 8; j++)
#pragma unroll
            for (int r = 0; r < 4; r++) acc[i][j][r] = 0;

    // ---- prologue: fill STAGES-1 stages ----
#pragma unroll
    for (int s = 0; s < STAGES - 1; s++) {
        const uint32_t sb = tiles + s * STAGE_BYTES;
        const int k0 = s * BK;
        CP_ASYNC_16(sb + sA0, gA0 + k0);
        CP_ASYNC_16(sb + sA1, gA1 + k0);
        CP_ASYNC_16(sb + sB0, gB0 + k0);
        CP_ASYNC_16(sb + sB1, gB1 + k0);
        CP_COMMIT();
    }

    // ---- mainloop ----
    for (int ki = 0; ki < NKI; ki++) {
        CP_WAIT(STAGES - 2);
        __syncthreads();

        // prefetch stage ki+STAGES-1
        {
            const int kj = ki + STAGES - 1;
            if (kj < NKI) {
                const uint32_t sb = tiles + (kj & (STAGES - 1)) * STAGE_BYTES;
                const int k0 = kj * BK;
                CP_ASYNC_16(sb + sA0, gA0 + k0);
                CP_ASYNC_16(sb + sA1, gA1 + k0);
                CP_ASYNC_16(sb + sB0, gB0 + k0);
                CP_ASYNC_16(sb + sB1, gB1 + k0);
            }
            CP_COMMIT();
        }

        const uint32_t sb = tiles + (ki & (STAGES - 1)) * STAGE_BYTES;
#pragma unroll
        for (int ks = 0; ks < 2; ks++) {
            // load ALL fragments for this 32-k slice first (6 LDSM), then 16 IMMA
            uint32_t a[2][4];
            uint32_t b[4][4];
#pragma unroll
            for (int i = 0; i < 2; i++)
                ldsm4(sb + a_base + i * (16 * ROWB) + ks * 32, a[i][0], a[i][1], a[i][2], a[i][3]);
#pragma unroll
            for (int jj = 0; jj < 4; jj++)
                ldsm4(sb + b_base + jj * (16 * ROWB) + ks * 32, b[jj][0], b[jj][1], b[jj][2], b[jj][3]);
#pragma unroll
            for (int jj = 0; jj < 4; jj++) {
                imma(acc[0][jj * 2 + 0], a[0], b[jj][0], b[jj][1]);
                imma(acc[0][jj * 2 + 1], a[0], b[jj][2], b[jj][3]);
                imma(acc[1][jj * 2 + 0], a[1], b[jj][0], b[jj][1]);
                imma(acc[1][jj * 2 + 1], a[1], b[jj][2], b[jj][3]);
            }
        }
    }

    // ---- epilogue ----
    const float ax = __uint_as_float(amax_bits[0]);
    const float aw = __uint_as_float(amax_bits[1]);
    const float sc = fmaxf(ax / 127.0f, 1e-8f) * fmaxf(aw / 127.0f, 1e-8f);

    const int g = lane >> 2;
    const int q = lane & 3;
#pragma unroll
    for (int i = 0; i < 2; i++) {
        const int row0 = m0 + wm + i * 16 + g;
#pragma unroll
        for (int j = 0; j < 8; j++) {
            const int col = n0 + wn + j * 8 + q * 2;
            const float2 bv = __ldg(reinterpret_cast<const float2*>(bias + col));
            float2 o0, o1;
            o0.x = fmaf((float)acc[i][j][0], sc, bv.x);
            o0.y = fmaf((float)acc[i][j][1], sc, bv.y);
            o1.x = fmaf((float)acc[i][j][2], sc, bv.x);
            o1.y = fmaf((float)acc[i][j][3], sc, bv.y);
            *reinterpret_cast<float2*>(out + (size_t)row0 * GN + col) = o0;
            *reinterpret_cast<float2*>(out + (size_t)(row0 + 8) * GN + col) = o1;
        }
    }
}

// ---------------- host launch ----------------
extern "C" void kernel_launch(void* const* d_in, const int* in_sizes, int n_in,
                              void* d_out, int out_size) {
    const float* x    = (const float*)d_in[0];
    const float* w    = (const float*)d_in[1];
    const float* bias = (const float*)d_in[2];
    float* out        = (float*)d_out;

    void *qx_ptr = nullptr, *qw_ptr = nullptr, *amax_ptr = nullptr;
    cudaGetSymbolAddress(&qx_ptr, g_qx);
    cudaGetSymbolAddress(&qw_ptr, g_qw);
    cudaGetSymbolAddress(&amax_ptr, g_amax_bits);
    unsigned* amax = (unsigned*)amax_ptr;

    // 4 launches total: gemm is #4 (-> global launch slot 6 for ncu -s 5 -c 1)
    init_kernel<<<1, 1>>>();
    absmax_both_kernel<<<2560, 256>>>((const float4*)x, (const float4*)w);
    quant_both_kernel<<<QBLK_X + QBLK_W, 256>>>((const float4*)x, (const float4*)w,
                                                (char4*)qx_ptr, (char4*)qw_ptr);

    cudaFuncSetAttribute(gemm_kernel, cudaFuncAttributeMaxDynamicSharedMemorySize, SMEM_REQ);
    gemm_kernel<<<dim3(GN / BN, GM / BM), 256, SMEM_REQ>>>(
        (const int8_t*)qx_ptr, (const int8_t*)qw_ptr, bias, out, amax);
}